// round 12
// baseline (speedup 1.0000x reference)
#include <cuda_runtime.h>
#include <cuda_bf16.h>
#include <cuda_fp16.h>
#include <cstdint>

#define D_MODEL 1024
#define NHEAD   16
#define HDIM    64
#define BATCH   4
#define SEQ     2048
#define MTOT    (BATCH*SEQ)   // 8192

// Q pre-scale: (1/sqrt(64)) * log2(e)  -> scores arrive in log2 domain
#define QSCALE  0.1803368801111204f

// ---------------- static device scratch (allocation-free) ----------------
__device__ __align__(16) __half g_xf[(size_t)MTOT*D_MODEL];          // x, fp16
__device__ __align__(16) __half g_wf[(size_t)4*D_MODEL*D_MODEL];     // Wq,Wk,Wv,Wo fp16
__device__ __align__(16) __half g_qh[(size_t)MTOT*D_MODEL];          // [B,H,S,D] pre-scaled
__device__ __align__(16) __half g_kh[(size_t)MTOT*D_MODEL];          // [B,H,S,D]
__device__ __align__(16) __half g_vt[(size_t)MTOT*D_MODEL];          // [B,H,D,S]
__device__ __align__(16) __half g_cf[(size_t)MTOT*D_MODEL];          // ctx, fp16 [B,S,D]

// ---------------- PTX helpers ----------------
__device__ __forceinline__ uint32_t smem_u32(const void* p) {
  uint32_t a;
  asm("{ .reg .u64 t; cvta.to.shared.u64 t, %1; cvt.u32.u64 %0, t; }" : "=r"(a) : "l"(p));
  return a;
}
__device__ __forceinline__ uint32_t h2_as_u32(__half2 h) {
  union { __half2 h; uint32_t u; } cvt;
  cvt.h = h;
  return cvt.u;
}
__device__ __forceinline__ void cp_async16(uint32_t saddr, const void* g) {
  asm volatile("cp.async.cg.shared.global [%0], [%1], 16;"
               :: "r"(saddr), "l"(__cvta_generic_to_global(g)) : "memory");
}
#define CP_COMMIT() asm volatile("cp.async.commit_group;" ::: "memory")
template<int N>
__device__ __forceinline__ void cp_wait() {
  asm volatile("cp.async.wait_group %0;" :: "n"(N) : "memory");
}
__device__ __forceinline__ void ldsm4(uint32_t* r, uint32_t addr) {
  asm volatile("ldmatrix.sync.aligned.m8n8.x4.shared.b16 {%0,%1,%2,%3}, [%4];"
               : "=r"(r[0]), "=r"(r[1]), "=r"(r[2]), "=r"(r[3]) : "r"(addr));
}
__device__ __forceinline__ void mma16816h(float* d, const uint32_t* a, const uint32_t* b) {
  asm volatile(
    "mma.sync.aligned.m16n8k16.row.col.f32.f16.f16.f32 "
    "{%0,%1,%2,%3}, {%4,%5,%6,%7}, {%8,%9}, {%0,%1,%2,%3};"
    : "+f"(d[0]), "+f"(d[1]), "+f"(d[2]), "+f"(d[3])
    : "r"(a[0]), "r"(a[1]), "r"(a[2]), "r"(a[3]), "r"(b[0]), "r"(b[1]));
}
// single-instruction 2^x on the MUFU pipe
__device__ __forceinline__ float fex2(float x) {
  float r;
  asm("ex2.approx.f32 %0, %1;" : "=f"(r) : "f"(x));
  return r;
}

// ---------------- convert: fp32 -> fp16 ----------------
__global__ __launch_bounds__(256) void convert_kernel(
    const float* __restrict__ x,
    const float* __restrict__ Wq, const float* __restrict__ Wk,
    const float* __restrict__ Wv, const float* __restrict__ Wo)
{
  const size_t XN = (size_t)MTOT * D_MODEL;
  const size_t WN = (size_t)D_MODEL * D_MODEL;
  size_t i = ((size_t)blockIdx.x * 256 + threadIdx.x) * 4;
  const float* src; __half* dst;
  if (i < XN) { src = x + i; dst = g_xf + i; }
  else {
    size_t w = i - XN;
    int widx = (int)(w / WN);
    size_t off = w - (size_t)widx * WN;
    const float* Ws = widx == 0 ? Wq : widx == 1 ? Wk : widx == 2 ? Wv : Wo;
    src = Ws + off;
    dst = g_wf + (size_t)widx * WN + off;
  }
  float4 v = *(const float4*)src;
  *(__half2*)(dst)     = __floats2half2_rn(v.x, v.y);
  *(__half2*)(dst + 2) = __floats2half2_rn(v.z, v.w);
}

// ---------------- mma.sync fp16 GEMM ----------------
// C[8192,1024] = A @ W^T + bias. CTA tile 128m x 256n, BK=64, 3 stages,
// 512 threads (16 warps @ 32x64 warp-tiles), fp32 accumulate.
// Mainloop uses explicit frag double-buffering: k-step ks+1's ldmatrix issue
// before ks's MMAs retire, hiding LDS latency.
#define BKC     64
#define NCHUNK  (D_MODEL/BKC)    // 16
#define ROWB    144              // 64 fp16 = 128B + 16B pad
#define A_OFF   0
#define B_OFF   (128*ROWB)       // 18432
#define STAGE   (B_OFF + 256*ROWB) // 55296
#define NST     3
#define GEMM_SMEM (NST*STAGE)    // 165888

template<int MODE>
__global__ __launch_bounds__(512, 1) void gemm_f16_kernel(
    const float* __restrict__ b0, const float* __restrict__ b1,
    const float* __restrict__ b2, float* __restrict__ outp)
{
  extern __shared__ __align__(128) char dynsm[];
  const uint32_t sb0 = smem_u32(dynsm);

  const int tid  = threadIdx.x;
  const int wid  = tid >> 5;
  const int lane = tid & 31;
  const int m0 = blockIdx.y * 128;
  const int n0 = blockIdx.x * 256;
  const int z  = (MODE == 0) ? blockIdx.z : 3;
  const int wrow0 = z * 1024 + n0;

  const __half* pA = (MODE == 0) ? g_xf : g_cf;

  // load plan: 3072 x 16B units per chunk, 6 per thread
  const int lrow0 = tid >> 3, lseg = tid & 7;

  auto load_chunk = [&](int c) {
    const uint32_t sb = sb0 + (uint32_t)(c % NST) * STAGE;
    const int k0 = c * BKC;
    #pragma unroll
    for (int i = 0; i < 2; i++) {
      const int row = lrow0 + i * 64;
      cp_async16(sb + A_OFF + (uint32_t)row * ROWB + (uint32_t)lseg * 16,
                 pA + (size_t)(m0 + row) * 1024 + k0 + lseg * 8);
    }
    #pragma unroll
    for (int i = 0; i < 4; i++) {
      const int row = lrow0 + i * 64;
      cp_async16(sb + B_OFF + (uint32_t)row * ROWB + (uint32_t)lseg * 16,
                 g_wf + (size_t)(wrow0 + row) * 1024 + k0 + lseg * 8);
    }
  };

  float acc[2][8][4];
  #pragma unroll
  for (int mt = 0; mt < 2; mt++)
    #pragma unroll
    for (int nt = 0; nt < 8; nt++)
      #pragma unroll
      for (int v = 0; v < 4; v++) acc[mt][nt][v] = 0.f;

  const int wr = wid >> 2;       // 0..3 -> m offset 32*wr
  const int wc = wid & 3;        // 0..3 -> n offset 64*wc
  const uint32_t aRowOff = (uint32_t)((lane & 7) + ((lane >> 3) & 1) * 8);
  const uint32_t aKoffB  = (uint32_t)((lane >> 4) * 16);
  // B ldsm4 lane map: groups (0-7,8-15,16-23,24-31) -> (nt,k0),(nt,k1),(nt+1,k0),(nt+1,k1)
  const uint32_t bRowOff = (uint32_t)((lane & 7) + (lane >> 4) * 8);
  const uint32_t bKoffB  = (uint32_t)(((lane >> 3) & 1) * 16);

  // warp-constant base offsets (keep addressing cheap)
  const uint32_t aBase = A_OFF + (uint32_t)(wr * 32 + aRowOff) * ROWB + aKoffB;
  const uint32_t bBase = B_OFF + (uint32_t)(wc * 64 + bRowOff) * ROWB + bKoffB;

  // double-buffered fragments
  uint32_t af[2][2][4], bf[2][4][4];

  load_chunk(0); CP_COMMIT();
  load_chunk(1); CP_COMMIT();

  #pragma unroll 1
  for (int c = 0; c < NCHUNK; c++) {
    cp_wait<1>();
    __syncthreads();
    const uint32_t sb = sb0 + (uint32_t)(c % NST) * STAGE;

    // k-step 0 fragments
    {
      ldsm4(af[0][0], sb + aBase);
      ldsm4(af[0][1], sb + aBase + 16 * ROWB);
      #pragma unroll
      for (int np = 0; np < 4; np++)
        ldsm4(bf[0][np], sb + bBase + (uint32_t)(np * 16) * ROWB);
    }
    if (c + 2 < NCHUNK) load_chunk(c + 2);
    CP_COMMIT();

    #pragma unroll
    for (int ks = 0; ks < 4; ks++) {
      const int cur = ks & 1, nxt = cur ^ 1;
      if (ks < 3) {
        const uint32_t kkB = (uint32_t)(ks + 1) * 32;
        ldsm4(af[nxt][0], sb + aBase + kkB);
        ldsm4(af[nxt][1], sb + aBase + 16 * ROWB + kkB);
        #pragma unroll
        for (int np = 0; np < 4; np++)
          ldsm4(bf[nxt][np], sb + bBase + (uint32_t)(np * 16) * ROWB + kkB);
      }
      #pragma unroll
      for (int np = 0; np < 4; np++) {
        mma16816h(acc[0][np*2+0], af[cur][0], bf[cur][np]);
        mma16816h(acc[1][np*2+0], af[cur][1], bf[cur][np]);
        mma16816h(acc[0][np*2+1], af[cur][0], bf[cur][np] + 2);
        mma16816h(acc[1][np*2+1], af[cur][1], bf[cur][np] + 2);
      }
    }
  }

  // ---------------- epilogue ----------------
  const float* bias = (MODE == 0) ? (z == 0 ? b0 : z == 1 ? b1 : b2) : b0;
  const int lrow = lane >> 2;
  const int lcol = (lane & 3) * 2;
  #pragma unroll
  for (int mt = 0; mt < 2; mt++) {
    #pragma unroll
    for (int nt = 0; nt < 8; nt++) {
      const int col = n0 + wc * 64 + nt * 8 + lcol;
      const float bx = bias[col], by = bias[col + 1];
      #pragma unroll
      for (int half = 0; half < 2; half++) {
        const int m = m0 + wr * 32 + mt * 16 + lrow + half * 8;
        float ox = acc[mt][nt][half * 2 + 0] + bx;
        float oy = acc[mt][nt][half * 2 + 1] + by;
        if (MODE == 0) {
          const int h  = col >> 6;
          const int dd = col & 63;
          const int bat = m >> 11;
          const int sq  = m & (SEQ - 1);
          const size_t bh = (size_t)bat * NHEAD + h;
          if (z == 0) {
            *(__half2*)(g_qh + ((bh * SEQ + sq) << 6) + dd) =
              __floats2half2_rn(ox * QSCALE, oy * QSCALE);
          } else if (z == 1) {
            *(__half2*)(g_kh + ((bh * SEQ + sq) << 6) + dd) =
              __floats2half2_rn(ox, oy);
          } else {
            g_vt[(bh * HDIM + dd)     * SEQ + sq] = __float2half(ox);
            g_vt[(bh * HDIM + dd + 1) * SEQ + sq] = __float2half(oy);
          }
        } else {
          float2 o; o.x = ox; o.y = oy;
          *(float2*)(outp + (size_t)m * D_MODEL + col) = o;
        }
      }
    }
  }
}

// ---------------- fp16 tensor-core flash attention ----------------
#define AROWB    144
#define AQ_BYTES (128*AROWB)
#define AKV_TILE (64*AROWB)
#define ATT_SMEM (AQ_BYTES + 6*AKV_TILE)

__global__ __launch_bounds__(256, 2) void attn_kernel()
{
  extern __shared__ __align__(128) char smemA[];
  const uint32_t sb = smem_u32(smemA);
  const uint32_t Qs = sb;
  const uint32_t Kb = sb + AQ_BYTES;
  const uint32_t Vb = Kb + 3*AKV_TILE;

  const int tid  = threadIdx.x;
  const int wid  = tid >> 5;
  const int lane = tid & 31;
  const int b  = blockIdx.z;
  const int h  = blockIdx.y;
  const int q0 = blockIdx.x * 128;
  const size_t bh = (size_t)b * NHEAD + h;

  const __half* Qg = g_qh + (bh * SEQ + q0) * HDIM;
  const __half* Kg = g_kh + bh * SEQ * HDIM;
  const __half* Vg = g_vt + bh * HDIM * SEQ;

  auto stage_kv = [&](int c) {
    const uint32_t kbuf = Kb + (uint32_t)(c % 3) * AKV_TILE;
    const uint32_t vbuf = Vb + (uint32_t)(c % 3) * AKV_TILE;
    const int kt = c * 64;
    #pragma unroll
    for (int i = 0; i < 2; i++) {
      const int u = tid + i * 256;
      const int row = u >> 3, seg = u & 7;
      cp_async16(kbuf + (uint32_t)row * AROWB + (uint32_t)seg * 16,
                 Kg + (size_t)(kt + row) * HDIM + seg * 8);
      cp_async16(vbuf + (uint32_t)row * AROWB + (uint32_t)seg * 16,
                 Vg + (size_t)row * SEQ + kt + seg * 8);
    }
  };
  {
    #pragma unroll
    for (int i = 0; i < 4; i++) {
      const int u = tid + i * 256;
      const int row = u >> 3, seg = u & 7;
      cp_async16(Qs + (uint32_t)row * AROWB + (uint32_t)seg * 16,
                 Qg + (size_t)row * HDIM + seg * 8);
    }
  }
  stage_kv(0); CP_COMMIT();
  stage_kv(1); CP_COMMIT();

  const uint32_t arow  = (uint32_t)((lane & 7) + ((lane >> 3) & 1) * 8);
  const uint32_t akoff = (uint32_t)((lane >> 4) * 16);
  const uint32_t brow  = (uint32_t)(lane & 7);
  const uint32_t bkoff = (uint32_t)(((lane >> 3) & 1) * 16 + (lane >> 4) * 32);

  uint32_t qf[4][4];
  float oc[8][4];
  #pragma unroll
  for (int nt = 0; nt < 8; nt++)
    #pragma unroll
    for (int v = 0; v < 4; v++) oc[nt][v] = 0.f;
  float l0 = 0.f, l1 = 0.f;

  #pragma unroll 1
  for (int c = 0; c < SEQ/64; c++) {
    cp_wait<1>();
    __syncthreads();
    if (c == 0) {
      #pragma unroll
      for (int ks = 0; ks < 4; ks++)
        ldsm4(qf[ks], Qs + (uint32_t)(wid * 16 + arow) * AROWB + (uint32_t)ks * 32 + akoff);
    }
    if (c + 2 < SEQ/64) stage_kv(c + 2);
    CP_COMMIT();

    const uint32_t kbuf = Kb + (uint32_t)(c % 3) * AKV_TILE;
    const uint32_t vbuf = Vb + (uint32_t)(c % 3) * AKV_TILE;

    // S = Q K^T  (scores already in log2 domain via QSCALE)
    float sc[8][4];
    #pragma unroll
    for (int nt = 0; nt < 8; nt++) {
      sc[nt][0] = sc[nt][1] = sc[nt][2] = sc[nt][3] = 0.f;
      uint32_t kbA[4], kbB[4];
      const uint32_t base = kbuf + (uint32_t)(nt * 8 + brow) * AROWB + bkoff;
      ldsm4(kbA, base);
      ldsm4(kbB, base + 64);
      mma16816h(sc[nt], qf[0], kbA);
      mma16816h(sc[nt], qf[1], kbA + 2);
      mma16816h(sc[nt], qf[2], kbB);
      mma16816h(sc[nt], qf[3], kbB + 2);
    }

    // P = 2^S (one MUFU op each), accumulate l, pack to fp16 A-frags
    uint32_t ph[8][2];
    #pragma unroll
    for (int nt = 0; nt < 8; nt++) {
      float e0 = fex2(sc[nt][0]);
      float e1 = fex2(sc[nt][1]);
      float e2 = fex2(sc[nt][2]);
      float e3 = fex2(sc[nt][3]);
      l0 += e0 + e1;
      l1 += e2 + e3;
      ph[nt][0] = h2_as_u32(__floats2half2_rn(e0, e1));
      ph[nt][1] = h2_as_u32(__floats2half2_rn(e2, e3));
    }

    // O += P V
    #pragma unroll
    for (int nt = 0; nt < 8; nt++) {
      uint32_t vbA[4], vbB[4];
      const uint32_t base = vbuf + (uint32_t)(nt * 8 + brow) * AROWB + bkoff;
      ldsm4(vbA, base);
      ldsm4(vbB, base + 64);
      uint32_t af[4];
      af[0] = ph[0][0]; af[1] = ph[0][1]; af[2] = ph[1][0]; af[3] = ph[1][1];
      mma16816h(oc[nt], af, vbA);
      af[0] = ph[2][0]; af[1] = ph[2][1]; af[2] = ph[3][0]; af[3] = ph[3][1];
      mma16816h(oc[nt], af, vbA + 2);
      af[0] = ph[4][0]; af[1] = ph[4][1]; af[2] = ph[5][0]; af[3] = ph[5][1];
      mma16816h(oc[nt], af, vbB);
      af[0] = ph[6][0]; af[1] = ph[6][1]; af[2] = ph[7][0]; af[3] = ph[7][1];
      mma16816h(oc[nt], af, vbB + 2);
    }
  }

  l0 += __shfl_xor_sync(0xffffffffu, l0, 1);
  l0 += __shfl_xor_sync(0xffffffffu, l0, 2);
  l1 += __shfl_xor_sync(0xffffffffu, l1, 1);
  l1 += __shfl_xor_sync(0xffffffffu, l1, 2);
  const float inv0 = 1.f / l0;
  const float inv1 = 1.f / l1;

  const int r0 = q0 + wid * 16 + (lane >> 2);
  const int r1 = r0 + 8;
  #pragma unroll
  for (int nt = 0; nt < 8; nt++) {
    const int dd = nt * 8 + (lane & 3) * 2;
    const int col = h * HDIM + dd;
    const size_t o0 = ((size_t)b * SEQ + r0) * D_MODEL + col;
    const size_t o1 = ((size_t)b * SEQ + r1) * D_MODEL + col;
    *(__half2*)(g_cf + o0) = __floats2half2_rn(oc[nt][0] * inv0, oc[nt][1] * inv0);
    *(__half2*)(g_cf + o1) = __floats2half2_rn(oc[nt][2] * inv1, oc[nt][3] * inv1);
  }
}

// ---------------- launch ----------------
extern "C" void kernel_launch(void* const* d_in, const int* in_sizes, int n_in,
                              void* d_out, int out_size)
{
  const float* x  = (const float*)d_in[0];
  const float* Wq = (const float*)d_in[1];
  const float* bq = (const float*)d_in[2];
  const float* Wk = (const float*)d_in[3];
  const float* bk = (const float*)d_in[4];
  const float* Wv = (const float*)d_in[5];
  const float* bv = (const float*)d_in[6];
  const float* Wo = (const float*)d_in[7];
  const float* bo = (const float*)d_in[8];
  float* out = (float*)d_out;

  cudaFuncSetAttribute(gemm_f16_kernel<0>,
                       cudaFuncAttributeMaxDynamicSharedMemorySize, GEMM_SMEM);
  cudaFuncSetAttribute(gemm_f16_kernel<1>,
                       cudaFuncAttributeMaxDynamicSharedMemorySize, GEMM_SMEM);
  cudaFuncSetAttribute(attn_kernel,
                       cudaFuncAttributeMaxDynamicSharedMemorySize, ATT_SMEM);

  const size_t total = (size_t)MTOT*D_MODEL + (size_t)4*D_MODEL*D_MODEL;
  convert_kernel<<<(unsigned)(total/4/256), 256>>>(x, Wq, Wk, Wv, Wo);

  gemm_f16_kernel<0><<<dim3(4, 64, 3), 512, GEMM_SMEM>>>(bq, bk, bv, nullptr);

  dim3 gAttn(SEQ / 128, NHEAD, BATCH);     // (16, 16, 4)
  attn_kernel<<<gAttn, 256, ATT_SMEM>>>();

  gemm_f16_kernel<1><<<dim3(4, 64, 1), 512, GEMM_SMEM>>>(bo, nullptr, nullptr, out);
}

// round 13
// speedup vs baseline: 1.0542x; 1.0542x over previous
#include <cuda_runtime.h>
#include <cuda_bf16.h>
#include <cuda_fp16.h>
#include <cstdint>

#define D_MODEL 1024
#define NHEAD   16
#define HDIM    64
#define BATCH   4
#define SEQ     2048
#define MTOT    (BATCH*SEQ)   // 8192

// Q pre-scale: (1/sqrt(64)) * log2(e)  -> scores arrive in log2 domain
#define QSCALE  0.1803368801111204f

// ---------------- static device scratch (allocation-free) ----------------
__device__ __align__(16) __half g_xf[(size_t)MTOT*D_MODEL];          // x, fp16
__device__ __align__(16) __half g_wf[(size_t)4*D_MODEL*D_MODEL];     // Wq,Wk,Wv,Wo fp16
__device__ __align__(16) __half g_qh[(size_t)MTOT*D_MODEL];          // [B,H,S,D] pre-scaled
__device__ __align__(16) __half g_kh[(size_t)MTOT*D_MODEL];          // [B,H,S,D]
__device__ __align__(16) __half g_vt[(size_t)MTOT*D_MODEL];          // [B,H,D,S]
__device__ __align__(16) __half g_cf[(size_t)MTOT*D_MODEL];          // ctx, fp16 [B,S,D]

// ---------------- PTX helpers ----------------
__device__ __forceinline__ uint32_t smem_u32(const void* p) {
  uint32_t a;
  asm("{ .reg .u64 t; cvta.to.shared.u64 t, %1; cvt.u32.u64 %0, t; }" : "=r"(a) : "l"(p));
  return a;
}
__device__ __forceinline__ uint32_t h2_as_u32(__half2 h) {
  union { __half2 h; uint32_t u; } cvt;
  cvt.h = h;
  return cvt.u;
}
__device__ __forceinline__ void cp_async16(uint32_t saddr, const void* g) {
  asm volatile("cp.async.cg.shared.global [%0], [%1], 16;"
               :: "r"(saddr), "l"(__cvta_generic_to_global(g)) : "memory");
}
#define CP_COMMIT() asm volatile("cp.async.commit_group;" ::: "memory")
template<int N>
__device__ __forceinline__ void cp_wait() {
  asm volatile("cp.async.wait_group %0;" :: "n"(N) : "memory");
}
__device__ __forceinline__ void ldsm4(uint32_t* r, uint32_t addr) {
  asm volatile("ldmatrix.sync.aligned.m8n8.x4.shared.b16 {%0,%1,%2,%3}, [%4];"
               : "=r"(r[0]), "=r"(r[1]), "=r"(r[2]), "=r"(r[3]) : "r"(addr));
}
__device__ __forceinline__ void mma16816h(float* d, const uint32_t* a, const uint32_t* b) {
  asm volatile(
    "mma.sync.aligned.m16n8k16.row.col.f32.f16.f16.f32 "
    "{%0,%1,%2,%3}, {%4,%5,%6,%7}, {%8,%9}, {%0,%1,%2,%3};"
    : "+f"(d[0]), "+f"(d[1]), "+f"(d[2]), "+f"(d[3])
    : "r"(a[0]), "r"(a[1]), "r"(a[2]), "r"(a[3]), "r"(b[0]), "r"(b[1]));
}
// single-instruction 2^x on the MUFU pipe
__device__ __forceinline__ float fex2(float x) {
  float r;
  asm("ex2.approx.f32 %0, %1;" : "=f"(r) : "f"(x));
  return r;
}

// ---------------- convert: fp32 -> fp16 ----------------
__global__ __launch_bounds__(256) void convert_kernel(
    const float* __restrict__ x,
    const float* __restrict__ Wq, const float* __restrict__ Wk,
    const float* __restrict__ Wv, const float* __restrict__ Wo)
{
  const size_t XN = (size_t)MTOT * D_MODEL;
  const size_t WN = (size_t)D_MODEL * D_MODEL;
  size_t i = ((size_t)blockIdx.x * 256 + threadIdx.x) * 4;
  const float* src; __half* dst;
  if (i < XN) { src = x + i; dst = g_xf + i; }
  else {
    size_t w = i - XN;
    int widx = (int)(w / WN);
    size_t off = w - (size_t)widx * WN;
    const float* Ws = widx == 0 ? Wq : widx == 1 ? Wk : widx == 2 ? Wv : Wo;
    src = Ws + off;
    dst = g_wf + (size_t)widx * WN + off;
  }
  float4 v = *(const float4*)src;
  *(__half2*)(dst)     = __floats2half2_rn(v.x, v.y);
  *(__half2*)(dst + 2) = __floats2half2_rn(v.z, v.w);
}

// ---------------- mma.sync fp16 GEMM ----------------
// C[8192,1024] = A @ W^T + bias. CTA tile 128m x 128n, BK=64, 3 stages,
// 256 threads (8 warps @ 32x64), 110.6KB smem -> 2 CTAs/SM so barrier
// gaps in one CTA are covered by the other.
#define BKC     64
#define NCHUNK  (D_MODEL/BKC)    // 16
#define ROWB    144              // 64 fp16 = 128B + 16B pad
#define A_OFF   0
#define B_OFF   (128*ROWB)       // 18432
#define STAGE   (B_OFF + 128*ROWB) // 36864
#define NST     3
#define GEMM_SMEM (NST*STAGE)    // 110592

template<int MODE>
__global__ __launch_bounds__(256, 2) void gemm_f16_kernel(
    const float* __restrict__ b0, const float* __restrict__ b1,
    const float* __restrict__ b2, float* __restrict__ outp)
{
  extern __shared__ __align__(128) char dynsm[];
  const uint32_t sb0 = smem_u32(dynsm);

  const int tid  = threadIdx.x;
  const int wid  = tid >> 5;
  const int lane = tid & 31;
  const int m0 = blockIdx.y * 128;
  const int n0 = blockIdx.x * 128;
  const int z  = (MODE == 0) ? blockIdx.z : 3;
  const int wrow0 = z * 1024 + n0;

  const __half* pA = (MODE == 0) ? g_xf : g_cf;

  // load plan: 2048 x 16B units per chunk, 8 per thread
  const int lrow0 = tid >> 3, lseg = tid & 7;   // 32 rows x 8 segs per 256 units

  auto load_chunk = [&](int c) {
    const uint32_t sb = sb0 + (uint32_t)(c % NST) * STAGE;
    const int k0 = c * BKC;
    #pragma unroll
    for (int i = 0; i < 4; i++) {
      const int row = lrow0 + i * 32;
      cp_async16(sb + A_OFF + (uint32_t)row * ROWB + (uint32_t)lseg * 16,
                 pA + (size_t)(m0 + row) * 1024 + k0 + lseg * 8);
    }
    #pragma unroll
    for (int i = 0; i < 4; i++) {
      const int row = lrow0 + i * 32;
      cp_async16(sb + B_OFF + (uint32_t)row * ROWB + (uint32_t)lseg * 16,
                 g_wf + (size_t)(wrow0 + row) * 1024 + k0 + lseg * 8);
    }
  };

  float acc[2][8][4];
  #pragma unroll
  for (int mt = 0; mt < 2; mt++)
    #pragma unroll
    for (int nt = 0; nt < 8; nt++)
      #pragma unroll
      for (int v = 0; v < 4; v++) acc[mt][nt][v] = 0.f;

  const int wr = wid >> 1;       // 0..3 -> m offset 32*wr
  const int wc = wid & 1;        // 0..1 -> n offset 64*wc
  const uint32_t aRowOff = (uint32_t)((lane & 7) + ((lane >> 3) & 1) * 8);
  const uint32_t aKoffB  = (uint32_t)((lane >> 4) * 16);
  // B ldsm4 lane map: groups (0-7,8-15,16-23,24-31) -> (nt,k0),(nt,k1),(nt+1,k0),(nt+1,k1)
  const uint32_t bRowOff = (uint32_t)((lane & 7) + (lane >> 4) * 8);
  const uint32_t bKoffB  = (uint32_t)(((lane >> 3) & 1) * 16);

  // warp-constant base offsets
  const uint32_t aBase = A_OFF + (uint32_t)(wr * 32 + aRowOff) * ROWB + aKoffB;
  const uint32_t bBase = B_OFF + (uint32_t)(wc * 64 + bRowOff) * ROWB + bKoffB;

  // double-buffered fragments
  uint32_t af[2][2][4], bf[2][4][4];

  load_chunk(0); CP_COMMIT();
  load_chunk(1); CP_COMMIT();

  #pragma unroll 1
  for (int c = 0; c < NCHUNK; c++) {
    cp_wait<1>();
    __syncthreads();
    const uint32_t sb = sb0 + (uint32_t)(c % NST) * STAGE;

    // k-step 0 fragments
    {
      ldsm4(af[0][0], sb + aBase);
      ldsm4(af[0][1], sb + aBase + 16 * ROWB);
      #pragma unroll
      for (int np = 0; np < 4; np++)
        ldsm4(bf[0][np], sb + bBase + (uint32_t)(np * 16) * ROWB);
    }
    if (c + 2 < NCHUNK) load_chunk(c + 2);
    CP_COMMIT();

    #pragma unroll
    for (int ks = 0; ks < 4; ks++) {
      const int cur = ks & 1, nxt = cur ^ 1;
      if (ks < 3) {
        const uint32_t kkB = (uint32_t)(ks + 1) * 32;
        ldsm4(af[nxt][0], sb + aBase + kkB);
        ldsm4(af[nxt][1], sb + aBase + 16 * ROWB + kkB);
        #pragma unroll
        for (int np = 0; np < 4; np++)
          ldsm4(bf[nxt][np], sb + bBase + (uint32_t)(np * 16) * ROWB + kkB);
      }
      #pragma unroll
      for (int np = 0; np < 4; np++) {
        mma16816h(acc[0][np*2+0], af[cur][0], bf[cur][np]);
        mma16816h(acc[1][np*2+0], af[cur][1], bf[cur][np]);
        mma16816h(acc[0][np*2+1], af[cur][0], bf[cur][np] + 2);
        mma16816h(acc[1][np*2+1], af[cur][1], bf[cur][np] + 2);
      }
    }
  }

  // ---------------- epilogue ----------------
  const float* bias = (MODE == 0) ? (z == 0 ? b0 : z == 1 ? b1 : b2) : b0;
  const int lrow = lane >> 2;
  const int lcol = (lane & 3) * 2;
  #pragma unroll
  for (int mt = 0; mt < 2; mt++) {
    #pragma unroll
    for (int nt = 0; nt < 8; nt++) {
      const int col = n0 + wc * 64 + nt * 8 + lcol;
      const float bx = bias[col], by = bias[col + 1];
      #pragma unroll
      for (int half = 0; half < 2; half++) {
        const int m = m0 + wr * 32 + mt * 16 + lrow + half * 8;
        float ox = acc[mt][nt][half * 2 + 0] + bx;
        float oy = acc[mt][nt][half * 2 + 1] + by;
        if (MODE == 0) {
          const int h  = col >> 6;
          const int dd = col & 63;
          const int bat = m >> 11;
          const int sq  = m & (SEQ - 1);
          const size_t bh = (size_t)bat * NHEAD + h;
          if (z == 0) {
            *(__half2*)(g_qh + ((bh * SEQ + sq) << 6) + dd) =
              __floats2half2_rn(ox * QSCALE, oy * QSCALE);
          } else if (z == 1) {
            *(__half2*)(g_kh + ((bh * SEQ + sq) << 6) + dd) =
              __floats2half2_rn(ox, oy);
          } else {
            g_vt[(bh * HDIM + dd)     * SEQ + sq] = __float2half(ox);
            g_vt[(bh * HDIM + dd + 1) * SEQ + sq] = __float2half(oy);
          }
        } else {
          float2 o; o.x = ox; o.y = oy;
          *(float2*)(outp + (size_t)m * D_MODEL + col) = o;
        }
      }
    }
  }
}

// ---------------- fp16 tensor-core flash attention ----------------
#define AROWB    144
#define AQ_BYTES (128*AROWB)
#define AKV_TILE (64*AROWB)
#define ATT_SMEM (AQ_BYTES + 6*AKV_TILE)

__global__ __launch_bounds__(256, 2) void attn_kernel()
{
  extern __shared__ __align__(128) char smemA[];
  const uint32_t sb = smem_u32(smemA);
  const uint32_t Qs = sb;
  const uint32_t Kb = sb + AQ_BYTES;
  const uint32_t Vb = Kb + 3*AKV_TILE;

  const int tid  = threadIdx.x;
  const int wid  = tid >> 5;
  const int lane = tid & 31;
  const int b  = blockIdx.z;
  const int h  = blockIdx.y;
  const int q0 = blockIdx.x * 128;
  const size_t bh = (size_t)b * NHEAD + h;

  const __half* Qg = g_qh + (bh * SEQ + q0) * HDIM;
  const __half* Kg = g_kh + bh * SEQ * HDIM;
  const __half* Vg = g_vt + bh * HDIM * SEQ;

  auto stage_kv = [&](int c) {
    const uint32_t kbuf = Kb + (uint32_t)(c % 3) * AKV_TILE;
    const uint32_t vbuf = Vb + (uint32_t)(c % 3) * AKV_TILE;
    const int kt = c * 64;
    #pragma unroll
    for (int i = 0; i < 2; i++) {
      const int u = tid + i * 256;
      const int row = u >> 3, seg = u & 7;
      cp_async16(kbuf + (uint32_t)row * AROWB + (uint32_t)seg * 16,
                 Kg + (size_t)(kt + row) * HDIM + seg * 8);
      cp_async16(vbuf + (uint32_t)row * AROWB + (uint32_t)seg * 16,
                 Vg + (size_t)row * SEQ + kt + seg * 8);
    }
  };
  {
    #pragma unroll
    for (int i = 0; i < 4; i++) {
      const int u = tid + i * 256;
      const int row = u >> 3, seg = u & 7;
      cp_async16(Qs + (uint32_t)row * AROWB + (uint32_t)seg * 16,
                 Qg + (size_t)row * HDIM + seg * 8);
    }
  }
  stage_kv(0); CP_COMMIT();
  stage_kv(1); CP_COMMIT();

  const uint32_t arow  = (uint32_t)((lane & 7) + ((lane >> 3) & 1) * 8);
  const uint32_t akoff = (uint32_t)((lane >> 4) * 16);
  const uint32_t brow  = (uint32_t)(lane & 7);
  const uint32_t bkoff = (uint32_t)(((lane >> 3) & 1) * 16 + (lane >> 4) * 32);

  uint32_t qf[4][4];
  float oc[8][4];
  #pragma unroll
  for (int nt = 0; nt < 8; nt++)
    #pragma unroll
    for (int v = 0; v < 4; v++) oc[nt][v] = 0.f;
  float l0 = 0.f, l1 = 0.f;

  #pragma unroll 1
  for (int c = 0; c < SEQ/64; c++) {
    cp_wait<1>();
    __syncthreads();
    if (c == 0) {
      #pragma unroll
      for (int ks = 0; ks < 4; ks++)
        ldsm4(qf[ks], Qs + (uint32_t)(wid * 16 + arow) * AROWB + (uint32_t)ks * 32 + akoff);
    }
    if (c + 2 < SEQ/64) stage_kv(c + 2);
    CP_COMMIT();

    const uint32_t kbuf = Kb + (uint32_t)(c % 3) * AKV_TILE;
    const uint32_t vbuf = Vb + (uint32_t)(c % 3) * AKV_TILE;

    // S = Q K^T  (scores already in log2 domain via QSCALE)
    float sc[8][4];
    #pragma unroll
    for (int nt = 0; nt < 8; nt++) {
      sc[nt][0] = sc[nt][1] = sc[nt][2] = sc[nt][3] = 0.f;
      uint32_t kbA[4], kbB[4];
      const uint32_t base = kbuf + (uint32_t)(nt * 8 + brow) * AROWB + bkoff;
      ldsm4(kbA, base);
      ldsm4(kbB, base + 64);
      mma16816h(sc[nt], qf[0], kbA);
      mma16816h(sc[nt], qf[1], kbA + 2);
      mma16816h(sc[nt], qf[2], kbB);
      mma16816h(sc[nt], qf[3], kbB + 2);
    }

    // P = 2^S (one MUFU op each), accumulate l, pack to fp16 A-frags
    uint32_t ph[8][2];
    #pragma unroll
    for (int nt = 0; nt < 8; nt++) {
      float e0 = fex2(sc[nt][0]);
      float e1 = fex2(sc[nt][1]);
      float e2 = fex2(sc[nt][2]);
      float e3 = fex2(sc[nt][3]);
      l0 += e0 + e1;
      l1 += e2 + e3;
      ph[nt][0] = h2_as_u32(__floats2half2_rn(e0, e1));
      ph[nt][1] = h2_as_u32(__floats2half2_rn(e2, e3));
    }

    // O += P V
    #pragma unroll
    for (int nt = 0; nt < 8; nt++) {
      uint32_t vbA[4], vbB[4];
      const uint32_t base = vbuf + (uint32_t)(nt * 8 + brow) * AROWB + bkoff;
      ldsm4(vbA, base);
      ldsm4(vbB, base + 64);
      uint32_t af[4];
      af[0] = ph[0][0]; af[1] = ph[0][1]; af[2] = ph[1][0]; af[3] = ph[1][1];
      mma16816h(oc[nt], af, vbA);
      af[0] = ph[2][0]; af[1] = ph[2][1]; af[2] = ph[3][0]; af[3] = ph[3][1];
      mma16816h(oc[nt], af, vbA + 2);
      af[0] = ph[4][0]; af[1] = ph[4][1]; af[2] = ph[5][0]; af[3] = ph[5][1];
      mma16816h(oc[nt], af, vbB);
      af[0] = ph[6][0]; af[1] = ph[6][1]; af[2] = ph[7][0]; af[3] = ph[7][1];
      mma16816h(oc[nt], af, vbB + 2);
    }
  }

  l0 += __shfl_xor_sync(0xffffffffu, l0, 1);
  l0 += __shfl_xor_sync(0xffffffffu, l0, 2);
  l1 += __shfl_xor_sync(0xffffffffu, l1, 1);
  l1 += __shfl_xor_sync(0xffffffffu, l1, 2);
  const float inv0 = 1.f / l0;
  const float inv1 = 1.f / l1;

  const int r0 = q0 + wid * 16 + (lane >> 2);
  const int r1 = r0 + 8;
  #pragma unroll
  for (int nt = 0; nt < 8; nt++) {
    const int dd = nt * 8 + (lane & 3) * 2;
    const int col = h * HDIM + dd;
    const size_t o0 = ((size_t)b * SEQ + r0) * D_MODEL + col;
    const size_t o1 = ((size_t)b * SEQ + r1) * D_MODEL + col;
    *(__half2*)(g_cf + o0) = __floats2half2_rn(oc[nt][0] * inv0, oc[nt][1] * inv0);
    *(__half2*)(g_cf + o1) = __floats2half2_rn(oc[nt][2] * inv1, oc[nt][3] * inv1);
  }
}

// ---------------- launch ----------------
extern "C" void kernel_launch(void* const* d_in, const int* in_sizes, int n_in,
                              void* d_out, int out_size)
{
  const float* x  = (const float*)d_in[0];
  const float* Wq = (const float*)d_in[1];
  const float* bq = (const float*)d_in[2];
  const float* Wk = (const float*)d_in[3];
  const float* bk = (const float*)d_in[4];
  const float* Wv = (const float*)d_in[5];
  const float* bv = (const float*)d_in[6];
  const float* Wo = (const float*)d_in[7];
  const float* bo = (const float*)d_in[8];
  float* out = (float*)d_out;

  cudaFuncSetAttribute(gemm_f16_kernel<0>,
                       cudaFuncAttributeMaxDynamicSharedMemorySize, GEMM_SMEM);
  cudaFuncSetAttribute(gemm_f16_kernel<1>,
                       cudaFuncAttributeMaxDynamicSharedMemorySize, GEMM_SMEM);
  cudaFuncSetAttribute(attn_kernel,
                       cudaFuncAttributeMaxDynamicSharedMemorySize, ATT_SMEM);

  const size_t total = (size_t)MTOT*D_MODEL + (size_t)4*D_MODEL*D_MODEL;
  convert_kernel<<<(unsigned)(total/4/256), 256>>>(x, Wq, Wk, Wv, Wo);

  gemm_f16_kernel<0><<<dim3(8, 64, 3), 256, GEMM_SMEM>>>(bq, bk, bv, nullptr);

  dim3 gAttn(SEQ / 128, NHEAD, BATCH);     // (16, 16, 4)
  attn_kernel<<<gAttn, 256, ATT_SMEM>>>();

  gemm_f16_kernel<1><<<dim3(8, 64, 1), 256, GEMM_SMEM>>>(bo, nullptr, nullptr, out);
}